// round 1
// baseline (speedup 1.0000x reference)
#include <cuda_runtime.h>
#include <cstdint>

// Problem constants
#define NB      64                 // batch
#define FT      51200              // 80*640 elements per (batch) slice
#define NCH     (NB * FT)          // 3,276,800 elements per channel (flattening unit)
#define NAUX    32
#define THRESH  20.0f
#define NTHREADS 256
#define J_PER_SLICE (FT / 4)       // 12800 float4s per (a,b) slice

// Scratch: strain peak bitmask (1 bit per element) + per-batch strain counts
__device__ unsigned g_strain_bits[NCH / 32];   // 409,600 B — lives in L2
__device__ int      g_c1[NB];

__device__ __forceinline__ unsigned peak_nibble(float4 v, float prev, float next) {
    // Strict local max on the flat array, height >= THRESH.
    // clip(x,0) in the reference is redundant because THRESH > 0 (see analysis).
    unsigned m = 0;
    m |= (v.x >= THRESH && v.x > prev && v.x > v.y) ? 1u : 0u;
    m |= (v.y >= THRESH && v.y > v.x  && v.y > v.z) ? 2u : 0u;
    m |= (v.z >= THRESH && v.z > v.y  && v.z > v.w) ? 4u : 0u;
    m |= (v.w >= THRESH && v.w > v.z  && v.w > next) ? 8u : 0u;
    return m;
}

// Kernel 1: strain peak mask -> packed bits + per-batch counts. One block per batch.
__global__ __launch_bounds__(NTHREADS)
void strain_mask_kernel(const float* __restrict__ qs) {
    const int b    = blockIdx.x;
    const int t    = threadIdx.x;
    const int lane = t & 31;
    const long base = (long)b * FT;

    int cnt = 0;
    #pragma unroll 2
    for (int j = t; j < J_PER_SLICE; j += NTHREADS) {
        const long L = base + 4L * j;                       // channel-local flat index
        float4 v = *reinterpret_cast<const float4*>(qs + L);
        float prev = __shfl_up_sync(0xffffffffu, v.w, 1);
        float next = __shfl_down_sync(0xffffffffu, v.x, 1);
        if (lane == 0)  prev = (L > 0)        ? qs[L - 1] : INFINITY;
        if (lane == 31) next = (L + 4 < NCH)  ? qs[L + 4] : INFINITY;

        unsigned nib = peak_nibble(v, prev, next);
        cnt += __popc(nib);

        // 8 lanes (consecutive j) share one 32-bit word; butterfly-OR within group of 8
        unsigned word = nib << (4 * (j & 7));
        word |= __shfl_xor_sync(0xffffffffu, word, 1);
        word |= __shfl_xor_sync(0xffffffffu, word, 2);
        word |= __shfl_xor_sync(0xffffffffu, word, 4);
        if ((lane & 7) == 0)
            g_strain_bits[(unsigned)(L >> 5)] = word;
    }

    // block-reduce count
    __shared__ int sred[NTHREADS / 32];
    #pragma unroll
    for (int o = 16; o > 0; o >>= 1) cnt += __shfl_xor_sync(0xffffffffu, cnt, o);
    if (lane == 0) sred[t >> 5] = cnt;
    __syncthreads();
    if (t < 32) {
        int s = (t < NTHREADS / 32) ? sred[t] : 0;
        #pragma unroll
        for (int o = 16; o > 0; o >>= 1) s += __shfl_xor_sync(0xffffffffu, s, o);
        if (t == 0) g_c1[b] = s;
    }
}

// Kernel 2: per (aux channel a, batch b): aux peak mask on the fly, intersect with
// strain bitmask, count, and write jac/ratio. Grid = (NB, NAUX).
__global__ __launch_bounds__(NTHREADS)
void aux_iou_kernel(const float* __restrict__ qa, float* __restrict__ out) {
    const int b    = blockIdx.x;   // 0..63
    const int a    = blockIdx.y;   // 0..31
    const int t    = threadIdx.x;
    const int lane = t & 31;

    const float* __restrict__ ch = qa + (long)a * NCH;
    const long base = (long)b * FT;

    int inter = 0, c2 = 0;
    #pragma unroll 2
    for (int j = t; j < J_PER_SLICE; j += NTHREADS) {
        const long L = base + 4L * j;
        float4 v = *reinterpret_cast<const float4*>(ch + L);
        float prev = __shfl_up_sync(0xffffffffu, v.w, 1);
        float next = __shfl_down_sync(0xffffffffu, v.x, 1);
        if (lane == 0)  prev = (L > 0)       ? ch[L - 1] : INFINITY;
        if (lane == 31) next = (L + 4 < NCH) ? ch[L + 4] : INFINITY;

        unsigned nib  = peak_nibble(v, prev, next);
        unsigned snib = (g_strain_bits[(unsigned)(L >> 5)] >> (unsigned)(L & 31)) & 0xFu;
        c2    += __popc(nib);
        inter += __popc(nib & snib);
    }

    // block-reduce (inter, c2)
    __shared__ int sInter[NTHREADS / 32];
    __shared__ int sC2[NTHREADS / 32];
    #pragma unroll
    for (int o = 16; o > 0; o >>= 1) {
        inter += __shfl_xor_sync(0xffffffffu, inter, o);
        c2    += __shfl_xor_sync(0xffffffffu, c2, o);
    }
    if (lane == 0) { sInter[t >> 5] = inter; sC2[t >> 5] = c2; }
    __syncthreads();
    if (t < 32) {
        int i2 = (t < NTHREADS / 32) ? sInter[t] : 0;
        int k2 = (t < NTHREADS / 32) ? sC2[t]    : 0;
        #pragma unroll
        for (int o = 16; o > 0; o >>= 1) {
            i2 += __shfl_xor_sync(0xffffffffu, i2, o);
            k2 += __shfl_xor_sync(0xffffffffu, k2, o);
        }
        if (t == 0) {
            const float fi  = (float)i2;
            const float fc1 = (float)g_c1[b];
            const float fc2 = (float)k2;
            const float un  = fc1 + fc2 - fi;
            float jac, ratio;
            if (fi == 0.0f && un == 0.0f) {        // zero_union -> 1.0 for both
                jac = 1.0f; ratio = 1.0f;
            } else {
                jac   = fi / un;                    // un > 0 here (inter <= union)
                ratio = (fc1 > 0.0f) ? (fi / fc1)   // c1==0 && inter==0 -> NaN -> 0
                                     : 0.0f;
            }
            const int idx = a * NB + b;            // iou.reshape(-1) layout
            out[idx]            = jac;
            out[NAUX * NB + idx] = ratio;          // corr follows iou in the flat output
        }
    }
}

extern "C" void kernel_launch(void* const* d_in, const int* in_sizes, int n_in,
                              void* d_out, int out_size) {
    const float* qt_strain = (const float*)d_in[0];   // [64, 80, 640]
    const float* qt_aux    = (const float*)d_in[1];   // [32, 64, 80, 640]
    float* out = (float*)d_out;                       // [2*32*64] = iou ++ corr

    strain_mask_kernel<<<NB, NTHREADS>>>(qt_strain);
    aux_iou_kernel<<<dim3(NB, NAUX), NTHREADS>>>(qt_aux, out);
}

// round 5
// speedup vs baseline: 1.6401x; 1.6401x over previous
#include <cuda_runtime.h>
#include <cstdint>

#define NB        64
#define FT        51200                  // 80*640 per batch slice
#define NCH       (NB * FT)              // flatten unit per channel
#define NAUX      32
#define THRESH    20.0f
#define NTHREADS  256                    // 8 warps
#define TILE      256                    // elements per warp-tile (32 lanes * 8)
#define EPL       8                      // elements per lane
#define TILES_PER_SLICE (FT / TILE)      // 200
#define K1_CHUNKS 25                     // 25 blocks * 8 warps = 200 tiles per slice

__device__ unsigned g_strain_bits[NCH / 32];      // 409,600 B, lives in L2
__device__ int      g_c1p[NB * K1_CHUNKS];        // per-block partial strain counts

// peak byte for 8 consecutive elements; x[0]=prev, x[1..8]=elems, x[9]=next.
// clip(x,0) in the reference is redundant since THRESH > 0.
__device__ __forceinline__ unsigned peak_byte8(const float x[10]) {
    unsigned m = 0;
#pragma unroll
    for (int i = 0; i < 8; i++) {
        float a = x[i + 1];
        if (a >= THRESH && a > x[i] && a > x[i + 2]) m |= (1u << i);
    }
    return m;
}

// Load 8 elems + neighbors for this lane. L = channel-local index of lane's first elem.
__device__ __forceinline__ unsigned lane_peak_byte(const float* __restrict__ ch,
                                                   unsigned L, int lane) {
    float4 v0 = *reinterpret_cast<const float4*>(ch + L);
    float4 v1 = *reinterpret_cast<const float4*>(ch + L + 4);
    float prev = __shfl_up_sync(0xffffffffu, v1.w, 1);
    float next = __shfl_down_sync(0xffffffffu, v0.x, 1);
    if (lane == 0)  prev = (L > 0)           ? ch[L - 1] : INFINITY;
    if (lane == 31) next = (L + EPL < NCH)   ? ch[L + EPL] : INFINITY;
    float x[10] = {prev, v0.x, v0.y, v0.z, v0.w, v1.x, v1.y, v1.z, v1.w, next};
    return peak_byte8(x);
}

// Kernel 1: strain peak bits + partial counts. grid = (K1_CHUNKS, NB).
// One warp-tile (256 elems) per warp; loopless.
__global__ __launch_bounds__(NTHREADS)
void strain_mask_kernel(const float* __restrict__ qs) {
    const int b    = blockIdx.y;
    const int t    = threadIdx.x;
    const int w    = t >> 5;
    const int lane = t & 31;
    const int tile = blockIdx.x * 8 + w;                 // 0..199
    const unsigned L = (unsigned)b * FT + (unsigned)tile * TILE + (unsigned)lane * EPL;

    unsigned m = lane_peak_byte(qs, L, lane);
    int cnt = __popc(m);

    // 4 lanes share one 32-bit word (lane*8 bits): OR within groups of 4
    unsigned word = m << (8 * (lane & 3));
    word |= __shfl_xor_sync(0xffffffffu, word, 1);
    word |= __shfl_xor_sync(0xffffffffu, word, 2);
    if ((lane & 3) == 0) g_strain_bits[L >> 5] = word;

    // reduce count: warp then block
#pragma unroll
    for (int o = 16; o > 0; o >>= 1) cnt += __shfl_xor_sync(0xffffffffu, cnt, o);
    __shared__ int sred[NTHREADS / 32];
    if (lane == 0) sred[w] = cnt;
    __syncthreads();
    if (t == 0) {
        int s = 0;
#pragma unroll
        for (int i = 0; i < NTHREADS / 32; i++) s += sred[i];
        g_c1p[b * K1_CHUNKS + blockIdx.x] = s;
    }
}

// Kernel 2: per (batch b, aux channel a). grid = (NB, NAUX).
__global__ __launch_bounds__(NTHREADS)
void aux_iou_kernel(const float* __restrict__ qa, float* __restrict__ out) {
    const int b    = blockIdx.x;
    const int a    = blockIdx.y;
    const int t    = threadIdx.x;
    const int w    = t >> 5;
    const int lane = t & 31;

    const float* __restrict__ ch = qa + (size_t)a * NCH;
    const unsigned base = (unsigned)b * FT;

    int inter = 0, c2 = 0;
    // warp w handles tiles w, w+8, ... (25 iterations)
    for (int tile = w; tile < TILES_PER_SLICE; tile += NTHREADS / 32) {
        const unsigned L = base + (unsigned)tile * TILE + (unsigned)lane * EPL;
        unsigned m = lane_peak_byte(ch, L, lane);
        unsigned sw = g_strain_bits[L >> 5];
        unsigned sbyte = (sw >> (8 * (lane & 3))) & 0xFFu;
        c2    += __popc(m);
        inter += __popc(m & sbyte);
    }

    // block reduce (inter, c2)
#pragma unroll
    for (int o = 16; o > 0; o >>= 1) {
        inter += __shfl_xor_sync(0xffffffffu, inter, o);
        c2    += __shfl_xor_sync(0xffffffffu, c2, o);
    }
    __shared__ int sInter[NTHREADS / 32];
    __shared__ int sC2[NTHREADS / 32];
    if (lane == 0) { sInter[w] = inter; sC2[w] = c2; }
    __syncthreads();

    if (t < 32) {
        int i2 = (t < NTHREADS / 32) ? sInter[t] : 0;
        int k2 = (t < NTHREADS / 32) ? sC2[t]    : 0;
        int c1 = (t < K1_CHUNKS)     ? g_c1p[b * K1_CHUNKS + t] : 0;
#pragma unroll
        for (int o = 16; o > 0; o >>= 1) {
            i2 += __shfl_xor_sync(0xffffffffu, i2, o);
            k2 += __shfl_xor_sync(0xffffffffu, k2, o);
            c1 += __shfl_xor_sync(0xffffffffu, c1, o);
        }
        if (t == 0) {
            const float fi  = (float)i2;
            const float fc1 = (float)c1;
            const float fc2 = (float)k2;
            const float un  = fc1 + fc2 - fi;
            float jac, ratio;
            if (fi == 0.0f && un == 0.0f) {          // zero_union -> 1.0 both
                jac = 1.0f; ratio = 1.0f;
            } else {
                jac   = fi / un;
                ratio = (fc1 > 0.0f) ? (fi / fc1) : 0.0f;   // NaN -> 0
            }
            const int idx = a * NB + b;
            out[idx]             = jac;
            out[NAUX * NB + idx] = ratio;
        }
    }
}

extern "C" void kernel_launch(void* const* d_in, const int* in_sizes, int n_in,
                              void* d_out, int out_size) {
    const float* qt_strain = (const float*)d_in[0];   // [64, 80, 640]
    const float* qt_aux    = (const float*)d_in[1];   // [32, 64, 80, 640]
    float* out = (float*)d_out;                       // [4096] = iou ++ corr

    strain_mask_kernel<<<dim3(K1_CHUNKS, NB), NTHREADS>>>(qt_strain);
    aux_iou_kernel<<<dim3(NB, NAUX), NTHREADS>>>(qt_aux, out);
}